// round 7
// baseline (speedup 1.0000x reference)
#include <cuda_runtime.h>
#include <cuda_bf16.h>
#include <math.h>

// Problem constants (from reference setup_inputs)
#define NMAX 50000
#define EMAX 800000
#define FIN  128
#define HC   256   // H*C1
#define H1   8
#define C1   32
#define SCAN_B 256
#define NBMAX ((NMAX + SCAN_B - 1) / SCAN_B)

// ---------------- device scratch (no allocs allowed) ----------------
__device__ int   g_is64;                      // edge_index dtype flag
__device__ int   g_deg[NMAX];
__device__ int   g_offs[NMAX + 1];
__device__ int   g_cursor[NMAX];
__device__ int   g_bsum[NBMAX];
__device__ int   g_boff[NBMAX];
__device__ int   g_esrc[EMAX + NMAX];
__device__ float g_h1[(size_t)NMAX * HC];     // x @ W1
__device__ float g_as[NMAX * H1];             // alpha_src layer1
__device__ float g_ad[NMAX * H1];             // alpha_dst layer1
__device__ float g_e[(size_t)(EMAX + NMAX) * H1]; // exp(leaky) [j][h]
__device__ float g_h2[NMAX];                  // layer-2 node scalar

// packed f32x2 helpers (sm_103a)
#define FMA2(d, a, b) \
    asm("fma.rn.f32x2 %0, %1, %2, %3;" : "=l"(d) : "l"(a), "l"(b), "l"(d))
#define PACK2(d, x, y) \
    asm("mov.b64 %0, {%1, %2};" : "=l"(d) : "r"(__float_as_uint(x)), "r"(__float_as_uint(y)))
#define UNPACK2(lo, hi, d) \
    asm("mov.b64 {%0, %1}, %2;" : "=f"(lo), "=f"(hi) : "l"(d))

// Read edge index entry idx (flat over the 2E-element buffer), dtype-agnostic.
__device__ __forceinline__ int edge_val(const void* ei, size_t idx, int is64) {
    if (is64) return (int)((const long long*)ei)[idx];
    return ((const int*)ei)[idx];
}

// ---------------- CSR build (dtype probe fused into init) ----------------
__global__ void init_deg_kernel(const void* ei, int E, int n) {
    int i = blockIdx.x * blockDim.x + threadIdx.x;
    if (i < n) g_deg[i] = 1;  // self loop
    if (i == 0) {
        // probe: interpret first entries as int64; real indices are < n,
        // int32 pairs misread as int64 are >= 2^32 w.h.p.
        const long long* p = (const long long*)ei;
        int cnt = 2 * E < 16 ? 2 * E : 16;
        int ok64 = 1;
        for (int k = 0; k < cnt; k++) {
            long long v = p[k];
            if (v < 0 || v >= (long long)n) { ok64 = 0; break; }
        }
        g_is64 = ok64;
    }
}

__global__ void count_kernel(const void* __restrict__ ei, int E) {
    int i = blockIdx.x * blockDim.x + threadIdx.x;
    if (i >= E) return;
    int d = edge_val(ei, (size_t)E + i, g_is64);
    atomicAdd(&g_deg[d], 1);
}

// ---- 3-phase scan (coalesced, full-grid) ----
__global__ __launch_bounds__(SCAN_B) void reduce_kernel(int n) {
    int i = blockIdx.x * SCAN_B + threadIdx.x;
    int v = (i < n) ? g_deg[i] : 0;
    #pragma unroll
    for (int o = 16; o > 0; o >>= 1) v += __shfl_xor_sync(0xFFFFFFFFu, v, o);
    __shared__ int w[SCAN_B / 32];
    if ((threadIdx.x & 31) == 0) w[threadIdx.x >> 5] = v;
    __syncthreads();
    if (threadIdx.x == 0) {
        int t = 0;
        #pragma unroll
        for (int k = 0; k < SCAN_B / 32; k++) t += w[k];
        g_bsum[blockIdx.x] = t;
    }
}

__global__ __launch_bounds__(SCAN_B) void bscan_kernel(int nb) {
    unsigned full = 0xFFFFFFFFu;
    int tid = threadIdx.x, lane = tid & 31, wid = tid >> 5;
    int v = (tid < nb) ? g_bsum[tid] : 0;
    int incl = v;
    #pragma unroll
    for (int o = 1; o < 32; o <<= 1) {
        int t = __shfl_up_sync(full, incl, o);
        if (lane >= o) incl += t;
    }
    __shared__ int w[SCAN_B / 32];
    if (lane == 31) w[wid] = incl;
    __syncthreads();
    if (wid == 0) {  // all 32 lanes run the shfl
        int orig = (lane < SCAN_B / 32) ? w[lane] : 0;
        int s = orig;
        #pragma unroll
        for (int o = 1; o < 32; o <<= 1) {
            int t = __shfl_up_sync(full, s, o);
            if (lane >= o) s += t;
        }
        if (lane < SCAN_B / 32) w[lane] = s - orig;
    }
    __syncthreads();
    if (tid < nb) g_boff[tid] = incl - v + w[wid];
}

__global__ __launch_bounds__(SCAN_B) void offs_kernel(int n) {
    unsigned full = 0xFFFFFFFFu;
    int tid = threadIdx.x, lane = tid & 31, wid = tid >> 5;
    int i = blockIdx.x * SCAN_B + tid;
    int v = (i < n) ? g_deg[i] : 0;
    int incl = v;
    #pragma unroll
    for (int o = 1; o < 32; o <<= 1) {
        int t = __shfl_up_sync(full, incl, o);
        if (lane >= o) incl += t;
    }
    __shared__ int w[SCAN_B / 32];
    if (lane == 31) w[wid] = incl;
    __syncthreads();
    if (wid == 0) {
        int orig = (lane < SCAN_B / 32) ? w[lane] : 0;
        int s = orig;
        #pragma unroll
        for (int o = 1; o < 32; o <<= 1) {
            int t = __shfl_up_sync(full, s, o);
            if (lane >= o) s += t;
        }
        if (lane < SCAN_B / 32) w[lane] = s - orig;
    }
    __syncthreads();
    if (i < n) {
        int off = g_boff[blockIdx.x] + (incl - v) + w[wid];
        g_offs[i] = off;
        g_cursor[i] = off;
        if (i == n - 1) g_offs[n] = off + v;
    }
}

__global__ void scatter_kernel(const void* __restrict__ ei, int E, int n) {
    int i = blockIdx.x * blockDim.x + threadIdx.x;
    if (i >= E + n) return;
    int is64 = g_is64;
    int s, d;
    if (i < E) {
        s = edge_val(ei, (size_t)i, is64);
        d = edge_val(ei, (size_t)E + i, is64);
    } else {
        s = d = i - E;
    }
    int pos = atomicAdd(&g_cursor[d], 1);
    g_esrc[pos] = s;
}

// ---------------- GEMM1 (f32x2 packed) + fused alpha epilogue ----------------
__global__ __launch_bounds__(256) void gemm1_kernel(
    const float* __restrict__ x, const float* __restrict__ W1,
    const float* __restrict__ a_src, const float* __restrict__ a_dst, int n) {
    __shared__ float xs[32][34];   // [kk][r], stride 34: 8B-aligned row pairs
    __shared__ float ws[32][256];  // [kk][col]
    int tid = threadIdx.x;
    int row0 = blockIdx.x * 32;
    int c0 = (tid & 63) * 4;       // 4 consecutive cols (within one head)
    int r0 = (tid >> 6) * 8;       // 8 consecutive rows

    unsigned long long acc2[4][4]; // [rowpair][col]; lo=even row, hi=odd row
    #pragma unroll
    for (int i = 0; i < 4; i++)
        #pragma unroll
        for (int j = 0; j < 4; j++) acc2[i][j] = 0ull;

    for (int k0 = 0; k0 < FIN; k0 += 32) {
        #pragma unroll
        for (int it = 0; it < 4; it++) {
            int idx = tid + it * 256;
            int r = idx >> 5, kk = idx & 31;
            int row = row0 + r;
            xs[kk][r] = (row < n) ? x[(size_t)row * FIN + k0 + kk] : 0.f;
        }
        #pragma unroll
        for (int it = 0; it < 8; it++) {
            int idx = (tid + it * 256) * 4;
            int kk = idx >> 8, cc = idx & 255;
            *(float4*)&ws[kk][cc] = *(const float4*)&W1[(size_t)(k0 + kk) * HC + cc];
        }
        __syncthreads();
        #pragma unroll
        for (int kk = 0; kk < 32; kk++) {
            float4 w = *(float4*)&ws[kk][c0];
            unsigned long long wx, wy, wz, ww;
            PACK2(wx, w.x, w.x); PACK2(wy, w.y, w.y);
            PACK2(wz, w.z, w.z); PACK2(ww, w.w, w.w);
            #pragma unroll
            for (int rp = 0; rp < 4; rp++) {
                unsigned long long ap =
                    *(const unsigned long long*)&xs[kk][r0 + 2 * rp];
                FMA2(acc2[rp][0], ap, wx);
                FMA2(acc2[rp][1], ap, wy);
                FMA2(acc2[rp][2], ap, wz);
                FMA2(acc2[rp][3], ap, ww);
            }
        }
        __syncthreads();
    }

    float accf[8][4];
    #pragma unroll
    for (int rp = 0; rp < 4; rp++)
        #pragma unroll
        for (int c = 0; c < 4; c++)
            UNPACK2(accf[2 * rp][c], accf[2 * rp + 1][c], acc2[rp][c]);

    #pragma unroll
    for (int rr = 0; rr < 8; rr++) {
        int row = row0 + r0 + rr;
        if (row < n) {
            float4 v = make_float4(accf[rr][0], accf[rr][1], accf[rr][2], accf[rr][3]);
            *(float4*)&g_h1[(size_t)row * HC + c0] = v;
        }
    }

    // fused alpha: per (row, head) dot with a_src/a_dst; 8 consecutive lanes reduce
    unsigned full = 0xFFFFFFFFu;
    float4 asv = *(const float4*)&a_src[c0 & 255];
    float4 adv = *(const float4*)&a_dst[c0 & 255];
    int head = (tid & 63) >> 3;
    #pragma unroll
    for (int rr = 0; rr < 8; rr++) {
        float ps = accf[rr][0] * asv.x + accf[rr][1] * asv.y
                 + accf[rr][2] * asv.z + accf[rr][3] * asv.w;
        float pd = accf[rr][0] * adv.x + accf[rr][1] * adv.y
                 + accf[rr][2] * adv.z + accf[rr][3] * adv.w;
        #pragma unroll
        for (int o = 1; o < 8; o <<= 1) {
            ps += __shfl_xor_sync(full, ps, o);
            pd += __shfl_xor_sync(full, pd, o);
        }
        int row = row0 + r0 + rr;
        if ((tid & 7) == 0 && row < n) {
            g_as[row * H1 + head] = ps;
            g_ad[row * H1 + head] = pd;
        }
    }
}

// ---------------- layer-1: 2-phase per-node block kernel ----------------
// Phase 1: 32 groups of 8 lanes (group=edge, lane=head): one 32B sector per
//          edge for g_as, coalesced g_e[j][h] store, deterministic smem reduce.
// Phase 2: warp per head, gather g_h1 (128B coalesced), fused bias/ELU/W2.
__global__ __launch_bounds__(256) void edge1_kernel(
    const float* __restrict__ bias1, const float* __restrict__ W2, int n) {
    int node = blockIdx.x;
    if (node >= n) return;
    int tid = threadIdx.x;
    int beg = g_offs[node], end = g_offs[node + 1];
    unsigned full = 0xFFFFFFFFu;

    __shared__ float sadv[H1];
    __shared__ float swsum[8][H1];   // per-warp partial sums
    __shared__ float sinv[H1];
    if (tid < H1) sadv[tid] = g_ad[node * H1 + tid];
    __syncthreads();

    // phase 1
    int grp = tid >> 3, hh = tid & 7;
    float psum = 0.f;
    for (int j = beg + grp; j < end; j += 32) {
        int sidx = g_esrc[j];                    // broadcast within group
        float e = g_as[sidx * H1 + hh] + sadv[hh];
        e = e > 0.f ? e : 0.2f * e;
        float ex = __expf(e);
        g_e[(size_t)j * H1 + hh] = ex;           // 32B contiguous per edge
        psum += ex;
    }
    // reduce over the 4 groups within each warp (deterministic)
    psum += __shfl_xor_sync(full, psum, 8);
    psum += __shfl_xor_sync(full, psum, 16);
    int wid = tid >> 5;
    if ((tid & 31) < 8) swsum[wid][hh] = psum;
    __syncthreads();
    if (tid < H1) {
        float t = 0.f;
        #pragma unroll
        for (int k = 0; k < 8; k++) t += swsum[k][tid];
        sinv[tid] = 1.f / (t + 1e-16f);
    }
    __syncthreads();

    // phase 2: warp per head
    int h = tid >> 5, lane = tid & 31;
    float acc0 = 0.f, acc1 = 0.f, acc2v = 0.f, acc3 = 0.f;
    size_t hc = (size_t)h * C1 + lane;
    int j = beg;
    for (; j + 4 <= end; j += 4) {
        int s0 = g_esrc[j], s1 = g_esrc[j + 1], s2 = g_esrc[j + 2], s3 = g_esrc[j + 3];
        float w0 = g_e[(size_t)j * H1 + h];      // broadcast; sector shared by 8 warps
        float w1 = g_e[(size_t)(j + 1) * H1 + h];
        float w2 = g_e[(size_t)(j + 2) * H1 + h];
        float w3 = g_e[(size_t)(j + 3) * H1 + h];
        acc0 += w0 * g_h1[(size_t)s0 * HC + hc];
        acc1 += w1 * g_h1[(size_t)s1 * HC + hc];
        acc2v += w2 * g_h1[(size_t)s2 * HC + hc];
        acc3 += w3 * g_h1[(size_t)s3 * HC + hc];
    }
    for (; j < end; j++) {
        int s0 = g_esrc[j];
        acc0 += g_e[(size_t)j * H1 + h] * g_h1[(size_t)s0 * HC + hc];
    }
    float acc = ((acc0 + acc1) + (acc2v + acc3)) * sinv[h];

    // bias + ELU + dot with W2 (layer-2 projection, Fout=1)
    float o1 = acc + bias1[h * C1 + lane];
    o1 = o1 > 0.f ? o1 : expm1f(o1);
    float p = o1 * W2[h * C1 + lane];
    #pragma unroll
    for (int o = 16; o > 0; o >>= 1) p += __shfl_xor_sync(full, p, o);

    __shared__ float part[H1];
    if (lane == 0) part[h] = p;
    __syncthreads();
    if (tid == 0) {
        float t = 0.f;
        #pragma unroll
        for (int i = 0; i < H1; i++) t += part[i];
        g_h2[node] = t;
    }
}

// ---------------- layer-2: single pass, no max + sigmoid ----------------
__global__ __launch_bounds__(256) void edge2_kernel(
    const float* __restrict__ as2p, const float* __restrict__ ad2p,
    const float* __restrict__ b2p, float* __restrict__ out, int n) {
    int warp = (blockIdx.x * blockDim.x + threadIdx.x) >> 5;
    int lane = threadIdx.x & 31;
    if (warp >= n) return;
    float a_s2 = as2p[0], a_d2 = ad2p[0], b2 = b2p[0];
    int beg = g_offs[warp], end = g_offs[warp + 1];
    float adv = g_h2[warp] * a_d2;
    unsigned full = 0xFFFFFFFFu;

    float s = 0.f, ws = 0.f;
    for (int j = beg + lane; j < end; j += 32) {
        float hv = g_h2[g_esrc[j]];
        float e = hv * a_s2 + adv;
        e = e > 0.f ? e : 0.2f * e;
        float ex = __expf(e);
        s += ex;
        ws += ex * hv;
    }
    #pragma unroll
    for (int o = 16; o > 0; o >>= 1) {
        s  += __shfl_xor_sync(full, s, o);
        ws += __shfl_xor_sync(full, ws, o);
    }
    if (lane == 0) {
        float v = ws / (s + 1e-16f) + b2;
        out[warp] = 1.f / (1.f + __expf(-v));
    }
}

// ---------------- launch ----------------
extern "C" void kernel_launch(void* const* d_in, const int* in_sizes, int n_in,
                              void* d_out, int out_size) {
    const float* x      = (const float*)d_in[0];
    const void*  ei     = d_in[1];             // int32 or int64 — probed on device
    const float* W1     = (const float*)d_in[2];
    const float* asrc1  = (const float*)d_in[3];
    const float* adst1  = (const float*)d_in[4];
    const float* bias1  = (const float*)d_in[5];
    const float* W2     = (const float*)d_in[6];
    const float* asrc2  = (const float*)d_in[7];
    const float* adst2  = (const float*)d_in[8];
    const float* bias2  = (const float*)d_in[9];
    float* out = (float*)d_out;

    int N = in_sizes[0] / FIN;
    int E = in_sizes[1] / 2;
    int NB = (N + SCAN_B - 1) / SCAN_B;

    // CSR build (by destination); dtype probe fused into init
    init_deg_kernel<<<(N + 255) / 256, 256>>>(ei, E, N);
    count_kernel<<<(E + 255) / 256, 256>>>(ei, E);
    reduce_kernel<<<NB, SCAN_B>>>(N);
    bscan_kernel<<<1, SCAN_B>>>(NB);
    offs_kernel<<<NB, SCAN_B>>>(N);
    scatter_kernel<<<(E + N + 255) / 256, 256>>>(ei, E, N);

    // layer 1 (alpha fused into gemm1 epilogue)
    gemm1_kernel<<<(N + 31) / 32, 256>>>(x, W1, asrc1, adst1, N);
    edge1_kernel<<<N, 256>>>(bias1, W2, N);

    // layer 2 (warp per node)
    edge2_kernel<<<(N * 32 + 255) / 256, 256>>>(asrc2, adst2, bias2, out, N);
}

// round 8
// speedup vs baseline: 1.1101x; 1.1101x over previous
#include <cuda_runtime.h>
#include <cuda_bf16.h>
#include <math.h>

// Problem constants (from reference setup_inputs)
#define NMAX 50000
#define EMAX 800000
#define FIN  128
#define HC   256   // H*C1
#define H1   8
#define C1   32
#define SCAN_B 256
#define NBMAX ((NMAX + SCAN_B - 1) / SCAN_B)
#define EPLANE (EMAX + NMAX)   // per-head plane stride in g_e

// ---------------- device scratch (no allocs allowed) ----------------
__device__ int   g_is64;                      // edge_index dtype flag
__device__ int   g_deg[NMAX];
__device__ int   g_offs[NMAX + 1];
__device__ int   g_cursor[NMAX];
__device__ int   g_bsum[NBMAX];
__device__ int   g_boff[NBMAX];
__device__ int   g_esrc[EMAX + NMAX];
__device__ __nv_bfloat16 g_h1bf[(size_t)NMAX * HC];  // x @ W1 (bf16)
__device__ float g_as[NMAX * H1];             // alpha_src layer1
__device__ float g_ad[NMAX * H1];             // alpha_dst layer1
__device__ float g_e[(size_t)EPLANE * H1];    // exp(leaky) per-head planes [h][j]
__device__ float g_h2[NMAX];                  // layer-2 node scalar

// packed f32x2 helpers (sm_103a)
#define FMA2(d, a, b) \
    asm("fma.rn.f32x2 %0, %1, %2, %3;" : "=l"(d) : "l"(a), "l"(b), "l"(d))
#define PACK2(d, x, y) \
    asm("mov.b64 %0, {%1, %2};" : "=l"(d) : "r"(__float_as_uint(x)), "r"(__float_as_uint(y)))
#define UNPACK2(lo, hi, d) \
    asm("mov.b64 {%0, %1}, %2;" : "=f"(lo), "=f"(hi) : "l"(d))

// Read edge index entry idx (flat over the 2E-element buffer), dtype-agnostic.
__device__ __forceinline__ int edge_val(const void* ei, size_t idx, int is64) {
    if (is64) return (int)((const long long*)ei)[idx];
    return ((const int*)ei)[idx];
}

// ---------------- CSR build (dtype probe fused into init) ----------------
__global__ void init_deg_kernel(const void* ei, int E, int n) {
    int i = blockIdx.x * blockDim.x + threadIdx.x;
    if (i < n) g_deg[i] = 1;  // self loop
    if (i == 0) {
        const long long* p = (const long long*)ei;
        int cnt = 2 * E < 16 ? 2 * E : 16;
        int ok64 = 1;
        for (int k = 0; k < cnt; k++) {
            long long v = p[k];
            if (v < 0 || v >= (long long)n) { ok64 = 0; break; }
        }
        g_is64 = ok64;
    }
}

__global__ void count_kernel(const void* __restrict__ ei, int E) {
    int i = blockIdx.x * blockDim.x + threadIdx.x;
    if (i >= E) return;
    int d = edge_val(ei, (size_t)E + i, g_is64);
    atomicAdd(&g_deg[d], 1);
}

// ---- 3-phase scan (coalesced, full-grid) ----
__global__ __launch_bounds__(SCAN_B) void reduce_kernel(int n) {
    int i = blockIdx.x * SCAN_B + threadIdx.x;
    int v = (i < n) ? g_deg[i] : 0;
    #pragma unroll
    for (int o = 16; o > 0; o >>= 1) v += __shfl_xor_sync(0xFFFFFFFFu, v, o);
    __shared__ int w[SCAN_B / 32];
    if ((threadIdx.x & 31) == 0) w[threadIdx.x >> 5] = v;
    __syncthreads();
    if (threadIdx.x == 0) {
        int t = 0;
        #pragma unroll
        for (int k = 0; k < SCAN_B / 32; k++) t += w[k];
        g_bsum[blockIdx.x] = t;
    }
}

__global__ __launch_bounds__(SCAN_B) void bscan_kernel(int nb) {
    unsigned full = 0xFFFFFFFFu;
    int tid = threadIdx.x, lane = tid & 31, wid = tid >> 5;
    int v = (tid < nb) ? g_bsum[tid] : 0;
    int incl = v;
    #pragma unroll
    for (int o = 1; o < 32; o <<= 1) {
        int t = __shfl_up_sync(full, incl, o);
        if (lane >= o) incl += t;
    }
    __shared__ int w[SCAN_B / 32];
    if (lane == 31) w[wid] = incl;
    __syncthreads();
    if (wid == 0) {  // all 32 lanes run the shfl
        int orig = (lane < SCAN_B / 32) ? w[lane] : 0;
        int s = orig;
        #pragma unroll
        for (int o = 1; o < 32; o <<= 1) {
            int t = __shfl_up_sync(full, s, o);
            if (lane >= o) s += t;
        }
        if (lane < SCAN_B / 32) w[lane] = s - orig;
    }
    __syncthreads();
    if (tid < nb) g_boff[tid] = incl - v + w[wid];
}

__global__ __launch_bounds__(SCAN_B) void offs_kernel(int n) {
    unsigned full = 0xFFFFFFFFu;
    int tid = threadIdx.x, lane = tid & 31, wid = tid >> 5;
    int i = blockIdx.x * SCAN_B + tid;
    int v = (i < n) ? g_deg[i] : 0;
    int incl = v;
    #pragma unroll
    for (int o = 1; o < 32; o <<= 1) {
        int t = __shfl_up_sync(full, incl, o);
        if (lane >= o) incl += t;
    }
    __shared__ int w[SCAN_B / 32];
    if (lane == 31) w[wid] = incl;
    __syncthreads();
    if (wid == 0) {
        int orig = (lane < SCAN_B / 32) ? w[lane] : 0;
        int s = orig;
        #pragma unroll
        for (int o = 1; o < 32; o <<= 1) {
            int t = __shfl_up_sync(full, s, o);
            if (lane >= o) s += t;
        }
        if (lane < SCAN_B / 32) w[lane] = s - orig;
    }
    __syncthreads();
    if (i < n) {
        int off = g_boff[blockIdx.x] + (incl - v) + w[wid];
        g_offs[i] = off;
        g_cursor[i] = off;
        if (i == n - 1) g_offs[n] = off + v;
    }
}

__global__ void scatter_kernel(const void* __restrict__ ei, int E, int n) {
    int i = blockIdx.x * blockDim.x + threadIdx.x;
    if (i >= E + n) return;
    int is64 = g_is64;
    int s, d;
    if (i < E) {
        s = edge_val(ei, (size_t)i, is64);
        d = edge_val(ei, (size_t)E + i, is64);
    } else {
        s = d = i - E;
    }
    int pos = atomicAdd(&g_cursor[d], 1);
    g_esrc[pos] = s;
}

// ---------------- GEMM1 (f32x2 packed) + fused alpha + bf16 store ------------
__global__ __launch_bounds__(256) void gemm1_kernel(
    const float* __restrict__ x, const float* __restrict__ W1,
    const float* __restrict__ a_src, const float* __restrict__ a_dst, int n) {
    __shared__ float xs[32][34];   // [kk][r], stride 34: 8B-aligned row pairs
    __shared__ float ws[32][256];  // [kk][col]
    int tid = threadIdx.x;
    int row0 = blockIdx.x * 32;
    int c0 = (tid & 63) * 4;       // 4 consecutive cols (within one head)
    int r0 = (tid >> 6) * 8;       // 8 consecutive rows

    unsigned long long acc2[4][4]; // [rowpair][col]; lo=even row, hi=odd row
    #pragma unroll
    for (int i = 0; i < 4; i++)
        #pragma unroll
        for (int j = 0; j < 4; j++) acc2[i][j] = 0ull;

    for (int k0 = 0; k0 < FIN; k0 += 32) {
        #pragma unroll
        for (int it = 0; it < 4; it++) {
            int idx = tid + it * 256;
            int r = idx >> 5, kk = idx & 31;
            int row = row0 + r;
            xs[kk][r] = (row < n) ? x[(size_t)row * FIN + k0 + kk] : 0.f;
        }
        #pragma unroll
        for (int it = 0; it < 8; it++) {
            int idx = (tid + it * 256) * 4;
            int kk = idx >> 8, cc = idx & 255;
            *(float4*)&ws[kk][cc] = *(const float4*)&W1[(size_t)(k0 + kk) * HC + cc];
        }
        __syncthreads();
        #pragma unroll
        for (int kk = 0; kk < 32; kk++) {
            float4 w = *(float4*)&ws[kk][c0];
            unsigned long long wx, wy, wz, ww;
            PACK2(wx, w.x, w.x); PACK2(wy, w.y, w.y);
            PACK2(wz, w.z, w.z); PACK2(ww, w.w, w.w);
            #pragma unroll
            for (int rp = 0; rp < 4; rp++) {
                unsigned long long ap =
                    *(const unsigned long long*)&xs[kk][r0 + 2 * rp];
                FMA2(acc2[rp][0], ap, wx);
                FMA2(acc2[rp][1], ap, wy);
                FMA2(acc2[rp][2], ap, wz);
                FMA2(acc2[rp][3], ap, ww);
            }
        }
        __syncthreads();
    }

    float accf[8][4];
    #pragma unroll
    for (int rp = 0; rp < 4; rp++)
        #pragma unroll
        for (int c = 0; c < 4; c++)
            UNPACK2(accf[2 * rp][c], accf[2 * rp + 1][c], acc2[rp][c]);

    // store h1 as bf16 (only consumer is edge1 pass B)
    #pragma unroll
    for (int rr = 0; rr < 8; rr++) {
        int row = row0 + r0 + rr;
        if (row < n) {
            __nv_bfloat162 p0 = __floats2bfloat162_rn(accf[rr][0], accf[rr][1]);
            __nv_bfloat162 p1 = __floats2bfloat162_rn(accf[rr][2], accf[rr][3]);
            uint2 v;
            v.x = *(unsigned*)&p0;
            v.y = *(unsigned*)&p1;
            *(uint2*)&g_h1bf[(size_t)row * HC + c0] = v;
        }
    }

    // fused alpha (fp32, from registers): 8 consecutive lanes reduce one (row, head)
    unsigned full = 0xFFFFFFFFu;
    float4 asv = *(const float4*)&a_src[c0 & 255];
    float4 adv = *(const float4*)&a_dst[c0 & 255];
    int head = (tid & 63) >> 3;
    #pragma unroll
    for (int rr = 0; rr < 8; rr++) {
        float ps = accf[rr][0] * asv.x + accf[rr][1] * asv.y
                 + accf[rr][2] * asv.z + accf[rr][3] * asv.w;
        float pd = accf[rr][0] * adv.x + accf[rr][1] * adv.y
                 + accf[rr][2] * adv.z + accf[rr][3] * adv.w;
        #pragma unroll
        for (int o = 1; o < 8; o <<= 1) {
            ps += __shfl_xor_sync(full, ps, o);
            pd += __shfl_xor_sync(full, pd, o);
        }
        int row = row0 + r0 + rr;
        if ((tid & 7) == 0 && row < n) {
            g_as[row * H1 + head] = ps;
            g_ad[row * H1 + head] = pd;
        }
    }
}

// ---------------- layer-1: R6 structure + bf16 paired-edge pass B ------------
__global__ __launch_bounds__(256) void edge1_kernel(
    const float* __restrict__ bias1, const float* __restrict__ W2, int n) {
    int node = blockIdx.x;
    if (node >= n) return;
    int tid = threadIdx.x;
    int h = tid >> 5, lane = tid & 31;
    int beg = g_offs[node], end = g_offs[node + 1];
    float adv = g_ad[node * H1 + h];
    float* eplane = &g_e[(size_t)h * EPLANE];
    unsigned full = 0xFFFFFFFFu;

    // pass A: gather logits, exp (no max: data bounded), coalesced plane cache
    float s = 0.f;
    for (int j = beg + lane; j < end; j += 32) {
        float e = g_as[g_esrc[j] * H1 + h] + adv;
        e = e > 0.f ? e : 0.2f * e;
        float ex = __expf(e);
        eplane[j] = ex;
        s += ex;
    }
    #pragma unroll
    for (int o = 16; o > 0; o >>= 1) s += __shfl_xor_sync(full, s, o);
    float inv = 1.f / (s + 1e-16f);

    // pass B: two 16-lane halves, each handles one edge/iter, lane = channel pair
    int sub = lane >> 4;        // 0 or 1
    int c2 = lane & 15;         // channel pair index (channels 2c2, 2c2+1)
    size_t base = (size_t)h * C1 + 2 * c2;
    float ax0 = 0.f, ay0 = 0.f, ax1 = 0.f, ay1 = 0.f;
    int j = beg;
    for (; j + 4 <= end; j += 4) {
        int ja = j + sub, jb = j + 2 + sub;
        int sa = g_esrc[ja], sb = g_esrc[jb];
        float wa = eplane[ja], wb = eplane[jb];
        __nv_bfloat162 va = *(const __nv_bfloat162*)&g_h1bf[(size_t)sa * HC + base];
        __nv_bfloat162 vb = *(const __nv_bfloat162*)&g_h1bf[(size_t)sb * HC + base];
        float2 fa = __bfloat1622float2(va);
        float2 fb = __bfloat1622float2(vb);
        ax0 += wa * fa.x; ay0 += wa * fa.y;
        ax1 += wb * fb.x; ay1 += wb * fb.y;
    }
    for (; j < end; j += 2) {
        int jj = j + sub;
        bool valid = jj < end;
        int sidx = valid ? g_esrc[jj] : g_esrc[beg];
        float w = valid ? eplane[jj] : 0.f;
        __nv_bfloat162 v = *(const __nv_bfloat162*)&g_h1bf[(size_t)sidx * HC + base];
        float2 f = __bfloat1622float2(v);
        ax0 += w * f.x; ay0 += w * f.y;
    }
    float ax = ax0 + ax1, ay = ay0 + ay1;
    // merge the two halves (lane i and i+16 hold the same channel pair)
    ax += __shfl_xor_sync(full, ax, 16);
    ay += __shfl_xor_sync(full, ay, 16);
    ax *= inv; ay *= inv;

    // bias + ELU + dot with W2 for this lane's 2 channels
    float b0 = bias1[h * C1 + 2 * c2], b1 = bias1[h * C1 + 2 * c2 + 1];
    float w20 = W2[h * C1 + 2 * c2], w21 = W2[h * C1 + 2 * c2 + 1];
    float o0 = ax + b0; o0 = o0 > 0.f ? o0 : expm1f(o0);
    float o1 = ay + b1; o1 = o1 > 0.f ? o1 : expm1f(o1);
    float p = o0 * w20 + o1 * w21;
    // reduce within each 16-lane half (halves are duplicates — don't cross 16)
    #pragma unroll
    for (int o = 1; o < 16; o <<= 1) p += __shfl_xor_sync(full, p, o);

    __shared__ float part[H1];
    if (lane == 0) part[h] = p;
    __syncthreads();
    if (tid == 0) {
        float t = 0.f;
        #pragma unroll
        for (int i = 0; i < H1; i++) t += part[i];
        g_h2[node] = t;
    }
}

// ---------------- layer-2: single pass, no max + sigmoid ----------------
__global__ __launch_bounds__(256) void edge2_kernel(
    const float* __restrict__ as2p, const float* __restrict__ ad2p,
    const float* __restrict__ b2p, float* __restrict__ out, int n) {
    int warp = (blockIdx.x * blockDim.x + threadIdx.x) >> 5;
    int lane = threadIdx.x & 31;
    if (warp >= n) return;
    float a_s2 = as2p[0], a_d2 = ad2p[0], b2 = b2p[0];
    int beg = g_offs[warp], end = g_offs[warp + 1];
    float adv = g_h2[warp] * a_d2;
    unsigned full = 0xFFFFFFFFu;

    float s = 0.f, ws = 0.f;
    for (int j = beg + lane; j < end; j += 32) {
        float hv = g_h2[g_esrc[j]];
        float e = hv * a_s2 + adv;
        e = e > 0.f ? e : 0.2f * e;
        float ex = __expf(e);
        s += ex;
        ws += ex * hv;
    }
    #pragma unroll
    for (int o = 16; o > 0; o >>= 1) {
        s  += __shfl_xor_sync(full, s, o);
        ws += __shfl_xor_sync(full, ws, o);
    }
    if (lane == 0) {
        float v = ws / (s + 1e-16f) + b2;
        out[warp] = 1.f / (1.f + __expf(-v));
    }
}

// ---------------- launch ----------------
extern "C" void kernel_launch(void* const* d_in, const int* in_sizes, int n_in,
                              void* d_out, int out_size) {
    const float* x      = (const float*)d_in[0];
    const void*  ei     = d_in[1];             // int32 or int64 — probed on device
    const float* W1     = (const float*)d_in[2];
    const float* asrc1  = (const float*)d_in[3];
    const float* adst1  = (const float*)d_in[4];
    const float* bias1  = (const float*)d_in[5];
    const float* W2     = (const float*)d_in[6];
    const float* asrc2  = (const float*)d_in[7];
    const float* adst2  = (const float*)d_in[8];
    const float* bias2  = (const float*)d_in[9];
    float* out = (float*)d_out;

    int N = in_sizes[0] / FIN;
    int E = in_sizes[1] / 2;
    int NB = (N + SCAN_B - 1) / SCAN_B;

    // CSR build (by destination); dtype probe fused into init
    init_deg_kernel<<<(N + 255) / 256, 256>>>(ei, E, N);
    count_kernel<<<(E + 255) / 256, 256>>>(ei, E);
    reduce_kernel<<<NB, SCAN_B>>>(N);
    bscan_kernel<<<1, SCAN_B>>>(NB);
    offs_kernel<<<NB, SCAN_B>>>(N);
    scatter_kernel<<<(E + N + 255) / 256, 256>>>(ei, E, N);

    // layer 1 (alpha fused into gemm1 epilogue)
    gemm1_kernel<<<(N + 31) / 32, 256>>>(x, W1, asrc1, adst1, N);
    edge1_kernel<<<N, 256>>>(bias1, W2, N);

    // layer 2 (warp per node)
    edge2_kernel<<<(N * 32 + 255) / 256, 256>>>(asrc2, adst2, bias2, out, N);
}

// round 9
// speedup vs baseline: 1.1116x; 1.0014x over previous
#include <cuda_runtime.h>
#include <cuda_bf16.h>
#include <math.h>

// Problem constants (from reference setup_inputs)
#define NMAX 50000
#define EMAX 800000
#define FIN  128
#define HC   256   // H*C1
#define H1   8
#define C1   32
#define SCAN_B 256
#define NBMAX ((NMAX + SCAN_B - 1) / SCAN_B)

// ---------------- device scratch (no allocs allowed) ----------------
__device__ int   g_is64;                      // edge_index dtype flag
__device__ int   g_deg[NMAX];
__device__ int   g_offs[NMAX + 1];
__device__ int   g_cursor[NMAX];
__device__ int   g_bsum[NBMAX];
__device__ int   g_boff[NBMAX];
__device__ int   g_esrc[EMAX + NMAX];
__device__ __nv_bfloat16 g_h1bf[(size_t)NMAX * HC];  // x @ W1 (bf16)
__device__ float g_as[NMAX * H1];             // alpha_src layer1
__device__ float g_ad[NMAX * H1];             // alpha_dst layer1
__device__ float g_h2[NMAX];                  // layer-2 node scalar

// packed f32x2 helpers (sm_103a)
#define FMA2(d, a, b) \
    asm("fma.rn.f32x2 %0, %1, %2, %3;" : "=l"(d) : "l"(a), "l"(b), "l"(d))
#define PACK2(d, x, y) \
    asm("mov.b64 %0, {%1, %2};" : "=l"(d) : "r"(__float_as_uint(x)), "r"(__float_as_uint(y)))
#define UNPACK2(lo, hi, d) \
    asm("mov.b64 {%0, %1}, %2;" : "=f"(lo), "=f"(hi) : "l"(d))

// Read edge index entry idx (flat over the 2E-element buffer), dtype-agnostic.
__device__ __forceinline__ int edge_val(const void* ei, size_t idx, int is64) {
    if (is64) return (int)((const long long*)ei)[idx];
    return ((const int*)ei)[idx];
}

// ---------------- CSR build (dtype probe fused into init) ----------------
__global__ void init_deg_kernel(const void* ei, int E, int n) {
    int i = blockIdx.x * blockDim.x + threadIdx.x;
    if (i < n) g_deg[i] = 1;  // self loop
    if (i == 0) {
        const long long* p = (const long long*)ei;
        int cnt = 2 * E < 16 ? 2 * E : 16;
        int ok64 = 1;
        for (int k = 0; k < cnt; k++) {
            long long v = p[k];
            if (v < 0 || v >= (long long)n) { ok64 = 0; break; }
        }
        g_is64 = ok64;
    }
}

__global__ void count_kernel(const void* __restrict__ ei, int E) {
    int i = blockIdx.x * blockDim.x + threadIdx.x;
    if (i >= E) return;
    int d = edge_val(ei, (size_t)E + i, g_is64);
    atomicAdd(&g_deg[d], 1);
}

// ---- 3-phase scan (coalesced, full-grid) ----
__global__ __launch_bounds__(SCAN_B) void reduce_kernel(int n) {
    int i = blockIdx.x * SCAN_B + threadIdx.x;
    int v = (i < n) ? g_deg[i] : 0;
    #pragma unroll
    for (int o = 16; o > 0; o >>= 1) v += __shfl_xor_sync(0xFFFFFFFFu, v, o);
    __shared__ int w[SCAN_B / 32];
    if ((threadIdx.x & 31) == 0) w[threadIdx.x >> 5] = v;
    __syncthreads();
    if (threadIdx.x == 0) {
        int t = 0;
        #pragma unroll
        for (int k = 0; k < SCAN_B / 32; k++) t += w[k];
        g_bsum[blockIdx.x] = t;
    }
}

__global__ __launch_bounds__(SCAN_B) void bscan_kernel(int nb) {
    unsigned full = 0xFFFFFFFFu;
    int tid = threadIdx.x, lane = tid & 31, wid = tid >> 5;
    int v = (tid < nb) ? g_bsum[tid] : 0;
    int incl = v;
    #pragma unroll
    for (int o = 1; o < 32; o <<= 1) {
        int t = __shfl_up_sync(full, incl, o);
        if (lane >= o) incl += t;
    }
    __shared__ int w[SCAN_B / 32];
    if (lane == 31) w[wid] = incl;
    __syncthreads();
    if (wid == 0) {  // all 32 lanes run the shfl
        int orig = (lane < SCAN_B / 32) ? w[lane] : 0;
        int s = orig;
        #pragma unroll
        for (int o = 1; o < 32; o <<= 1) {
            int t = __shfl_up_sync(full, s, o);
            if (lane >= o) s += t;
        }
        if (lane < SCAN_B / 32) w[lane] = s - orig;
    }
    __syncthreads();
    if (tid < nb) g_boff[tid] = incl - v + w[wid];
}

__global__ __launch_bounds__(SCAN_B) void offs_kernel(int n) {
    unsigned full = 0xFFFFFFFFu;
    int tid = threadIdx.x, lane = tid & 31, wid = tid >> 5;
    int i = blockIdx.x * SCAN_B + tid;
    int v = (i < n) ? g_deg[i] : 0;
    int incl = v;
    #pragma unroll
    for (int o = 1; o < 32; o <<= 1) {
        int t = __shfl_up_sync(full, incl, o);
        if (lane >= o) incl += t;
    }
    __shared__ int w[SCAN_B / 32];
    if (lane == 31) w[wid] = incl;
    __syncthreads();
    if (wid == 0) {
        int orig = (lane < SCAN_B / 32) ? w[lane] : 0;
        int s = orig;
        #pragma unroll
        for (int o = 1; o < 32; o <<= 1) {
            int t = __shfl_up_sync(full, s, o);
            if (lane >= o) s += t;
        }
        if (lane < SCAN_B / 32) w[lane] = s - orig;
    }
    __syncthreads();
    if (i < n) {
        int off = g_boff[blockIdx.x] + (incl - v) + w[wid];
        g_offs[i] = off;
        g_cursor[i] = off;
        if (i == n - 1) g_offs[n] = off + v;
    }
}

__global__ void scatter_kernel(const void* __restrict__ ei, int E, int n) {
    int i = blockIdx.x * blockDim.x + threadIdx.x;
    if (i >= E + n) return;
    int is64 = g_is64;
    int s, d;
    if (i < E) {
        s = edge_val(ei, (size_t)i, is64);
        d = edge_val(ei, (size_t)E + i, is64);
    } else {
        s = d = i - E;
    }
    int pos = atomicAdd(&g_cursor[d], 1);
    g_esrc[pos] = s;
}

// ---------------- GEMM1 (f32x2 packed) + fused alpha + bf16 store ------------
__global__ __launch_bounds__(256) void gemm1_kernel(
    const float* __restrict__ x, const float* __restrict__ W1,
    const float* __restrict__ a_src, const float* __restrict__ a_dst, int n) {
    __shared__ float xs[32][34];   // [kk][r], stride 34: 8B-aligned row pairs
    __shared__ float ws[32][256];  // [kk][col]
    int tid = threadIdx.x;
    int row0 = blockIdx.x * 32;
    int c0 = (tid & 63) * 4;       // 4 consecutive cols (within one head)
    int r0 = (tid >> 6) * 8;       // 8 consecutive rows

    unsigned long long acc2[4][4]; // [rowpair][col]; lo=even row, hi=odd row
    #pragma unroll
    for (int i = 0; i < 4; i++)
        #pragma unroll
        for (int j = 0; j < 4; j++) acc2[i][j] = 0ull;

    for (int k0 = 0; k0 < FIN; k0 += 32) {
        #pragma unroll
        for (int it = 0; it < 4; it++) {
            int idx = tid + it * 256;
            int r = idx >> 5, kk = idx & 31;
            int row = row0 + r;
            xs[kk][r] = (row < n) ? x[(size_t)row * FIN + k0 + kk] : 0.f;
        }
        #pragma unroll
        for (int it = 0; it < 8; it++) {
            int idx = (tid + it * 256) * 4;
            int kk = idx >> 8, cc = idx & 255;
            *(float4*)&ws[kk][cc] = *(const float4*)&W1[(size_t)(k0 + kk) * HC + cc];
        }
        __syncthreads();
        #pragma unroll
        for (int kk = 0; kk < 32; kk++) {
            float4 w = *(float4*)&ws[kk][c0];
            unsigned long long wx, wy, wz, ww;
            PACK2(wx, w.x, w.x); PACK2(wy, w.y, w.y);
            PACK2(wz, w.z, w.z); PACK2(ww, w.w, w.w);
            #pragma unroll
            for (int rp = 0; rp < 4; rp++) {
                unsigned long long ap =
                    *(const unsigned long long*)&xs[kk][r0 + 2 * rp];
                FMA2(acc2[rp][0], ap, wx);
                FMA2(acc2[rp][1], ap, wy);
                FMA2(acc2[rp][2], ap, wz);
                FMA2(acc2[rp][3], ap, ww);
            }
        }
        __syncthreads();
    }

    float accf[8][4];
    #pragma unroll
    for (int rp = 0; rp < 4; rp++)
        #pragma unroll
        for (int c = 0; c < 4; c++)
            UNPACK2(accf[2 * rp][c], accf[2 * rp + 1][c], acc2[rp][c]);

    // store h1 as bf16 (only consumer is edge1 stage 2)
    #pragma unroll
    for (int rr = 0; rr < 8; rr++) {
        int row = row0 + r0 + rr;
        if (row < n) {
            __nv_bfloat162 p0 = __floats2bfloat162_rn(accf[rr][0], accf[rr][1]);
            __nv_bfloat162 p1 = __floats2bfloat162_rn(accf[rr][2], accf[rr][3]);
            uint2 v;
            v.x = *(unsigned*)&p0;
            v.y = *(unsigned*)&p1;
            *(uint2*)&g_h1bf[(size_t)row * HC + c0] = v;
        }
    }

    // fused alpha (fp32, from registers): 8 consecutive lanes reduce one (row, head)
    unsigned full = 0xFFFFFFFFu;
    float4 asv = *(const float4*)&a_src[c0 & 255];
    float4 adv = *(const float4*)&a_dst[c0 & 255];
    int head = (tid & 63) >> 3;
    #pragma unroll
    for (int rr = 0; rr < 8; rr++) {
        float ps = accf[rr][0] * asv.x + accf[rr][1] * asv.y
                 + accf[rr][2] * asv.z + accf[rr][3] * asv.w;
        float pd = accf[rr][0] * adv.x + accf[rr][1] * adv.y
                 + accf[rr][2] * adv.z + accf[rr][3] * adv.w;
        #pragma unroll
        for (int o = 1; o < 8; o <<= 1) {
            ps += __shfl_xor_sync(full, ps, o);
            pd += __shfl_xor_sync(full, pd, o);
        }
        int row = row0 + r0 + rr;
        if ((tid & 7) == 0 && row < n) {
            g_as[row * H1 + head] = ps;
            g_ad[row * H1 + head] = pd;
        }
    }
}

// ---------------- layer-1: tiled single-sweep, smem-staged weights -----------
// Per 32-edge tile:
//   stage 1 (all 256 threads; grp=edge, hh=head): gather g_as (1 sector/edge,
//     block-wide), exp -> smem sexp[edge][head] (padded), ssrc[edge].
//   stage 2 (warp per head, 16-lane halves): bf16 h1 gather weighted by smem,
//     per-head exp-sum read back from smem. Softmax divide deferred to the end.
__global__ __launch_bounds__(256) void edge1_kernel(
    const float* __restrict__ bias1, const float* __restrict__ W2, int n) {
    int node = blockIdx.x;
    if (node >= n) return;
    int tid = threadIdx.x;
    int h = tid >> 5, lane = tid & 31;
    int beg = g_offs[node], end = g_offs[node + 1];
    unsigned full = 0xFFFFFFFFu;

    __shared__ float sexp[32][9];   // [edge][head], pad 9 kills bank conflicts
    __shared__ int   ssrc[32];
    __shared__ float sadv[H1];
    __shared__ float part[H1];
    if (tid < H1) sadv[tid] = g_ad[node * H1 + tid];
    __syncthreads();

    int grp = tid >> 3, hh = tid & 7;      // stage-1 mapping
    int sub = lane >> 4, c2 = lane & 15;   // stage-2 mapping
    size_t base = (size_t)h * C1 + 2 * c2;

    float ax = 0.f, ay = 0.f, ssum = 0.f;

    for (int t = beg; t < end; t += 32) {
        int cnt = min(32, end - t);

        // stage 1: one (edge, head) per thread
        float ex = 0.f;
        if (grp < cnt) {
            int sidx = g_esrc[t + grp];                  // 4 distinct addrs/warp
            if (hh == 0) ssrc[grp] = sidx;
            float e = g_as[sidx * H1 + hh] + sadv[hh];   // 4 sectors/warp
            e = e > 0.f ? e : 0.2f * e;
            ex = __expf(e);
        }
        sexp[grp][hh] = ex;
        __syncthreads();

        // stage 2: head-warp aggregates; halves take alternating edges
        for (int k = sub; k < cnt; k += 2) {
            float w = sexp[k][h];                        // 2-way broadcast LDS
            int sx = ssrc[k];
            __nv_bfloat162 v = *(const __nv_bfloat162*)&g_h1bf[(size_t)sx * HC + base];
            float2 f = __bfloat1622float2(v);
            ax += w * f.x;
            ay += w * f.y;
        }
        // per-head exp sum for this tile (lane = edge)
        ssum += (lane < cnt) ? sexp[lane][h] : 0.f;
        __syncthreads();   // protect smem before next tile overwrites
    }

    // reduce ssum across the warp; merge the two halves of ax/ay
    #pragma unroll
    for (int o = 16; o > 0; o >>= 1) ssum += __shfl_xor_sync(full, ssum, o);
    ax += __shfl_xor_sync(full, ax, 16);
    ay += __shfl_xor_sync(full, ay, 16);
    float inv = 1.f / (ssum + 1e-16f);
    ax *= inv; ay *= inv;

    // bias + ELU + dot with W2 for this lane's 2 channels
    float b0 = bias1[h * C1 + 2 * c2], b1 = bias1[h * C1 + 2 * c2 + 1];
    float w20 = W2[h * C1 + 2 * c2], w21 = W2[h * C1 + 2 * c2 + 1];
    float o0 = ax + b0; o0 = o0 > 0.f ? o0 : expm1f(o0);
    float o1 = ay + b1; o1 = o1 > 0.f ? o1 : expm1f(o1);
    float p = o0 * w20 + o1 * w21;
    // reduce within each 16-lane half (halves hold identical values)
    #pragma unroll
    for (int o = 1; o < 16; o <<= 1) p += __shfl_xor_sync(full, p, o);

    if (lane == 0) part[h] = p;
    __syncthreads();
    if (tid == 0) {
        float t = 0.f;
        #pragma unroll
        for (int i = 0; i < H1; i++) t += part[i];
        g_h2[node] = t;
    }
}

// ---------------- layer-2: single pass, no max + sigmoid ----------------
__global__ __launch_bounds__(256) void edge2_kernel(
    const float* __restrict__ as2p, const float* __restrict__ ad2p,
    const float* __restrict__ b2p, float* __restrict__ out, int n) {
    int warp = (blockIdx.x * blockDim.x + threadIdx.x) >> 5;
    int lane = threadIdx.x & 31;
    if (warp >= n) return;
    float a_s2 = as2p[0], a_d2 = ad2p[0], b2 = b2p[0];
    int beg = g_offs[warp], end = g_offs[warp + 1];
    float adv = g_h2[warp] * a_d2;
    unsigned full = 0xFFFFFFFFu;

    float s = 0.f, ws = 0.f;
    for (int j = beg + lane; j < end; j += 32) {
        float hv = g_h2[g_esrc[j]];
        float e = hv * a_s2 + adv;
        e = e > 0.f ? e : 0.2f * e;
        float ex = __expf(e);
        s += ex;
        ws += ex * hv;
    }
    #pragma unroll
    for (int o = 16; o > 0; o >>= 1) {
        s  += __shfl_xor_sync(full, s, o);
        ws += __shfl_xor_sync(full, ws, o);
    }
    if (lane == 0) {
        float v = ws / (s + 1e-16f) + b2;
        out[warp] = 1.f / (1.f + __expf(-v));
    }
}

// ---------------- launch ----------------
extern "C" void kernel_launch(void* const* d_in, const int* in_sizes, int n_in,
                              void* d_out, int out_size) {
    const float* x      = (const float*)d_in[0];
    const void*  ei     = d_in[1];             // int32 or int64 — probed on device
    const float* W1     = (const float*)d_in[2];
    const float* asrc1  = (const float*)d_in[3];
    const float* adst1  = (const float*)d_in[4];
    const float* bias1  = (const float*)d_in[5];
    const float* W2     = (const float*)d_in[6];
    const float* asrc2  = (const float*)d_in[7];
    const float* adst2  = (const float*)d_in[8];
    const float* bias2  = (const float*)d_in[9];
    float* out = (float*)d_out;

    int N = in_sizes[0] / FIN;
    int E = in_sizes[1] / 2;
    int NB = (N + SCAN_B - 1) / SCAN_B;

    // CSR build (by destination); dtype probe fused into init
    init_deg_kernel<<<(N + 255) / 256, 256>>>(ei, E, N);
    count_kernel<<<(E + 255) / 256, 256>>>(ei, E);
    reduce_kernel<<<NB, SCAN_B>>>(N);
    bscan_kernel<<<1, SCAN_B>>>(NB);
    offs_kernel<<<NB, SCAN_B>>>(N);
    scatter_kernel<<<(E + N + 255) / 256, 256>>>(ei, E, N);

    // layer 1 (alpha fused into gemm1 epilogue)
    gemm1_kernel<<<(N + 31) / 32, 256>>>(x, W1, asrc1, adst1, N);
    edge1_kernel<<<N, 256>>>(bias1, W2, N);

    // layer 2 (warp per node)
    edge2_kernel<<<(N * 32 + 255) / 256, 256>>>(asrc2, adst2, bias2, out, N);
}

// round 10
// speedup vs baseline: 1.8980x; 1.7075x over previous
#include <cuda_runtime.h>
#include <cuda_bf16.h>
#include <math.h>

// Problem constants (from reference setup_inputs)
#define NMAX 50000
#define EMAX 800000
#define FIN  128
#define HC   256   // H*C1
#define H1   8
#define C1   32
#define SCAN_B 256
#define NBMAX ((NMAX + SCAN_B - 1) / SCAN_B)

// ---------------- device scratch (no allocs allowed) ----------------
__device__ int   g_is64;                      // edge_index dtype flag
__device__ int   g_deg[NMAX];
__device__ int   g_offs[NMAX + 1];
__device__ int   g_cursor[NMAX];
__device__ int   g_bsum[NBMAX];
__device__ int   g_boff[NBMAX];
__device__ int   g_esrc[EMAX + NMAX];
__device__ __nv_bfloat16 g_h1bf[(size_t)NMAX * HC];  // x @ W1 (bf16)
__device__ float g_as[NMAX * H1];             // alpha_src layer1
__device__ float g_ad[NMAX * H1];             // alpha_dst layer1
__device__ float g_h2[NMAX];                  // layer-2 node scalar

// packed f32x2 helpers (sm_103a)
#define FMA2(d, a, b) \
    asm("fma.rn.f32x2 %0, %1, %2, %3;" : "=l"(d) : "l"(a), "l"(b), "l"(d))
#define PACK2(d, x, y) \
    asm("mov.b64 %0, {%1, %2};" : "=l"(d) : "r"(__float_as_uint(x)), "r"(__float_as_uint(y)))
#define UNPACK2(lo, hi, d) \
    asm("mov.b64 {%0, %1}, %2;" : "=f"(lo), "=f"(hi) : "l"(d))

// Read edge index entry idx (flat over the 2E-element buffer), dtype-agnostic.
__device__ __forceinline__ int edge_val(const void* ei, size_t idx, int is64) {
    if (is64) return (int)((const long long*)ei)[idx];
    return ((const int*)ei)[idx];
}

// ---------------- CSR build (dtype probe fused into init) ----------------
__global__ void init_deg_kernel(const void* ei, int E, int n) {
    int i = blockIdx.x * blockDim.x + threadIdx.x;
    if (i < n) g_deg[i] = 1;  // self loop
    if (i == 0) {
        const long long* p = (const long long*)ei;
        int cnt = 2 * E < 16 ? 2 * E : 16;
        int ok64 = 1;
        for (int k = 0; k < cnt; k++) {
            long long v = p[k];
            if (v < 0 || v >= (long long)n) { ok64 = 0; break; }
        }
        g_is64 = ok64;
    }
}

__global__ void count_kernel(const void* __restrict__ ei, int E) {
    int i = blockIdx.x * blockDim.x + threadIdx.x;
    if (i >= E) return;
    int d = edge_val(ei, (size_t)E + i, g_is64);
    atomicAdd(&g_deg[d], 1);
}

// ---- 3-phase scan (coalesced, full-grid) ----
__global__ __launch_bounds__(SCAN_B) void reduce_kernel(int n) {
    int i = blockIdx.x * SCAN_B + threadIdx.x;
    int v = (i < n) ? g_deg[i] : 0;
    #pragma unroll
    for (int o = 16; o > 0; o >>= 1) v += __shfl_xor_sync(0xFFFFFFFFu, v, o);
    __shared__ int w[SCAN_B / 32];
    if ((threadIdx.x & 31) == 0) w[threadIdx.x >> 5] = v;
    __syncthreads();
    if (threadIdx.x == 0) {
        int t = 0;
        #pragma unroll
        for (int k = 0; k < SCAN_B / 32; k++) t += w[k];
        g_bsum[blockIdx.x] = t;
    }
}

__global__ __launch_bounds__(SCAN_B) void bscan_kernel(int nb) {
    unsigned full = 0xFFFFFFFFu;
    int tid = threadIdx.x, lane = tid & 31, wid = tid >> 5;
    int v = (tid < nb) ? g_bsum[tid] : 0;
    int incl = v;
    #pragma unroll
    for (int o = 1; o < 32; o <<= 1) {
        int t = __shfl_up_sync(full, incl, o);
        if (lane >= o) incl += t;
    }
    __shared__ int w[SCAN_B / 32];
    if (lane == 31) w[wid] = incl;
    __syncthreads();
    if (wid == 0) {  // all 32 lanes run the shfl
        int orig = (lane < SCAN_B / 32) ? w[lane] : 0;
        int s = orig;
        #pragma unroll
        for (int o = 1; o < 32; o <<= 1) {
            int t = __shfl_up_sync(full, s, o);
            if (lane >= o) s += t;
        }
        if (lane < SCAN_B / 32) w[lane] = s - orig;
    }
    __syncthreads();
    if (tid < nb) g_boff[tid] = incl - v + w[wid];
}

__global__ __launch_bounds__(SCAN_B) void offs_kernel(int n) {
    unsigned full = 0xFFFFFFFFu;
    int tid = threadIdx.x, lane = tid & 31, wid = tid >> 5;
    int i = blockIdx.x * SCAN_B + tid;
    int v = (i < n) ? g_deg[i] : 0;
    int incl = v;
    #pragma unroll
    for (int o = 1; o < 32; o <<= 1) {
        int t = __shfl_up_sync(full, incl, o);
        if (lane >= o) incl += t;
    }
    __shared__ int w[SCAN_B / 32];
    if (lane == 31) w[wid] = incl;
    __syncthreads();
    if (wid == 0) {
        int orig = (lane < SCAN_B / 32) ? w[lane] : 0;
        int s = orig;
        #pragma unroll
        for (int o = 1; o < 32; o <<= 1) {
            int t = __shfl_up_sync(full, s, o);
            if (lane >= o) s += t;
        }
        if (lane < SCAN_B / 32) w[lane] = s - orig;
    }
    __syncthreads();
    if (i < n) {
        int off = g_boff[blockIdx.x] + (incl - v) + w[wid];
        g_offs[i] = off;
        g_cursor[i] = off;
        if (i == n - 1) g_offs[n] = off + v;
    }
}

// ---------------- fused GEMM1 + scatter (independent; overlap on-chip) -------
// Blocks [0, NBg): GEMM1 h1=x@W1 (f32x2 packed) + fused alpha + bf16 store.
// Blocks [NBg, ...): CSR scatter.
__global__ __launch_bounds__(256) void gemm_scatter_kernel(
    const float* __restrict__ x, const float* __restrict__ W1,
    const float* __restrict__ a_src, const float* __restrict__ a_dst,
    const void* __restrict__ ei, int E, int n, int NBg) {
    __shared__ float xs[32][34];   // [kk][r], stride 34: 8B-aligned row pairs
    __shared__ float ws[32][256];  // [kk][col]
    int tid = threadIdx.x;

    if ((int)blockIdx.x >= NBg) {
        // ---- scatter branch ----
        int i = ((int)blockIdx.x - NBg) * 256 + tid;
        if (i >= E + n) return;
        int is64 = g_is64;
        int s, d;
        if (i < E) {
            s = edge_val(ei, (size_t)i, is64);
            d = edge_val(ei, (size_t)E + i, is64);
        } else {
            s = d = i - E;
        }
        int pos = atomicAdd(&g_cursor[d], 1);
        g_esrc[pos] = s;
        return;
    }

    // ---- GEMM branch ----
    int row0 = blockIdx.x * 32;
    int c0 = (tid & 63) * 4;       // 4 consecutive cols (within one head)
    int r0 = (tid >> 6) * 8;       // 8 consecutive rows

    unsigned long long acc2[4][4]; // [rowpair][col]; lo=even row, hi=odd row
    #pragma unroll
    for (int i = 0; i < 4; i++)
        #pragma unroll
        for (int j = 0; j < 4; j++) acc2[i][j] = 0ull;

    for (int k0 = 0; k0 < FIN; k0 += 32) {
        #pragma unroll
        for (int it = 0; it < 4; it++) {
            int idx = tid + it * 256;
            int r = idx >> 5, kk = idx & 31;
            int row = row0 + r;
            xs[kk][r] = (row < n) ? x[(size_t)row * FIN + k0 + kk] : 0.f;
        }
        #pragma unroll
        for (int it = 0; it < 8; it++) {
            int idx = (tid + it * 256) * 4;
            int kk = idx >> 8, cc = idx & 255;
            *(float4*)&ws[kk][cc] = *(const float4*)&W1[(size_t)(k0 + kk) * HC + cc];
        }
        __syncthreads();
        #pragma unroll
        for (int kk = 0; kk < 32; kk++) {
            float4 w = *(float4*)&ws[kk][c0];
            unsigned long long wx, wy, wz, ww;
            PACK2(wx, w.x, w.x); PACK2(wy, w.y, w.y);
            PACK2(wz, w.z, w.z); PACK2(ww, w.w, w.w);
            #pragma unroll
            for (int rp = 0; rp < 4; rp++) {
                unsigned long long ap =
                    *(const unsigned long long*)&xs[kk][r0 + 2 * rp];
                FMA2(acc2[rp][0], ap, wx);
                FMA2(acc2[rp][1], ap, wy);
                FMA2(acc2[rp][2], ap, wz);
                FMA2(acc2[rp][3], ap, ww);
            }
        }
        __syncthreads();
    }

    float accf[8][4];
    #pragma unroll
    for (int rp = 0; rp < 4; rp++)
        #pragma unroll
        for (int c = 0; c < 4; c++)
            UNPACK2(accf[2 * rp][c], accf[2 * rp + 1][c], acc2[rp][c]);

    // store h1 as bf16 (only consumer is edge1)
    #pragma unroll
    for (int rr = 0; rr < 8; rr++) {
        int row = row0 + r0 + rr;
        if (row < n) {
            __nv_bfloat162 p0 = __floats2bfloat162_rn(accf[rr][0], accf[rr][1]);
            __nv_bfloat162 p1 = __floats2bfloat162_rn(accf[rr][2], accf[rr][3]);
            uint2 v;
            v.x = *(unsigned*)&p0;
            v.y = *(unsigned*)&p1;
            *(uint2*)&g_h1bf[(size_t)row * HC + c0] = v;
        }
    }

    // fused alpha (fp32, from registers): 8 consecutive lanes reduce one (row, head)
    unsigned full = 0xFFFFFFFFu;
    float4 asv = *(const float4*)&a_src[c0 & 255];
    float4 adv = *(const float4*)&a_dst[c0 & 255];
    int head = (tid & 63) >> 3;
    #pragma unroll
    for (int rr = 0; rr < 8; rr++) {
        float ps = accf[rr][0] * asv.x + accf[rr][1] * asv.y
                 + accf[rr][2] * asv.z + accf[rr][3] * asv.w;
        float pd = accf[rr][0] * adv.x + accf[rr][1] * adv.y
                 + accf[rr][2] * adv.z + accf[rr][3] * adv.w;
        #pragma unroll
        for (int o = 1; o < 8; o <<= 1) {
            ps += __shfl_xor_sync(full, ps, o);
            pd += __shfl_xor_sync(full, pd, o);
        }
        int row = row0 + r0 + rr;
        if ((tid & 7) == 0 && row < n) {
            g_as[row * H1 + head] = ps;
            g_ad[row * H1 + head] = pd;
        }
    }
}

// ---------------- layer-1: warp-per-node, all heads in one LDG.128 -----------
// Lane l owns channels [8l, 8l+8) (head = l/4). Per edge: one broadcast esrc
// load, one 1-sector g_as gather, ONE uint4 load of the full bf16 row slice.
// Softmax normalization deferred to a single divide at the end. No barriers.
__global__ __launch_bounds__(256) void edge1_kernel(
    const float* __restrict__ bias1, const float* __restrict__ W2, int n) {
    int node = (blockIdx.x * blockDim.x + threadIdx.x) >> 5;
    int lane = threadIdx.x & 31;
    if (node >= n) return;
    unsigned full = 0xFFFFFFFFu;
    int h = lane >> 2;                 // head (4 lanes per head)
    size_t colbase = (size_t)lane * 8; // = h*C1 + (lane&3)*8
    float adv = g_ad[node * H1 + h];   // 8 distinct addrs = 1 sector
    int beg = g_offs[node], end = g_offs[node + 1];

    float acc0[8], acc1[8];
    #pragma unroll
    for (int c = 0; c < 8; c++) { acc0[c] = 0.f; acc1[c] = 0.f; }
    float ssum = 0.f;

    int j = beg;
    for (; j + 2 <= end; j += 2) {   // 2 independent edges in flight
        int sa = g_esrc[j], sb = g_esrc[j + 1];
        float ea = g_as[sa * H1 + h] + adv;
        float eb = g_as[sb * H1 + h] + adv;
        ea = ea > 0.f ? ea : 0.2f * ea;
        eb = eb > 0.f ? eb : 0.2f * eb;
        float wa = __expf(ea), wb = __expf(eb);
        ssum += wa + wb;
        uint4 va = *(const uint4*)&g_h1bf[(size_t)sa * HC + colbase];
        uint4 vb = *(const uint4*)&g_h1bf[(size_t)sb * HC + colbase];
        const __nv_bfloat162* pa = (const __nv_bfloat162*)&va;
        const __nv_bfloat162* pb = (const __nv_bfloat162*)&vb;
        #pragma unroll
        for (int q = 0; q < 4; q++) {
            float2 fa = __bfloat1622float2(pa[q]);
            float2 fb = __bfloat1622float2(pb[q]);
            acc0[2 * q]     += wa * fa.x;
            acc0[2 * q + 1] += wa * fa.y;
            acc1[2 * q]     += wb * fb.x;
            acc1[2 * q + 1] += wb * fb.y;
        }
    }
    if (j < end) {
        int sa = g_esrc[j];
        float ea = g_as[sa * H1 + h] + adv;
        ea = ea > 0.f ? ea : 0.2f * ea;
        float wa = __expf(ea);
        ssum += wa;
        uint4 va = *(const uint4*)&g_h1bf[(size_t)sa * HC + colbase];
        const __nv_bfloat162* pa = (const __nv_bfloat162*)&va;
        #pragma unroll
        for (int q = 0; q < 4; q++) {
            float2 fa = __bfloat1622float2(pa[q]);
            acc0[2 * q]     += wa * fa.x;
            acc0[2 * q + 1] += wa * fa.y;
        }
    }
    float inv = 1.f / (ssum + 1e-16f);

    // epilogue: bias + ELU + dot with W2 over this lane's 8 channels
    float4 b0 = *(const float4*)&bias1[colbase];
    float4 b1 = *(const float4*)&bias1[colbase + 4];
    float4 w0 = *(const float4*)&W2[colbase];
    float4 w1 = *(const float4*)&W2[colbase + 4];
    float bb[8] = {b0.x, b0.y, b0.z, b0.w, b1.x, b1.y, b1.z, b1.w};
    float ww[8] = {w0.x, w0.y, w0.z, w0.w, w1.x, w1.y, w1.z, w1.w};
    float p = 0.f;
    #pragma unroll
    for (int c = 0; c < 8; c++) {
        float o = (acc0[c] + acc1[c]) * inv + bb[c];
        o = o > 0.f ? o : expm1f(o);
        p += o * ww[c];
    }
    #pragma unroll
    for (int o = 16; o > 0; o >>= 1) p += __shfl_xor_sync(full, p, o);
    if (lane == 0) g_h2[node] = p;
}

// ---------------- layer-2: single pass, no max + sigmoid ----------------
__global__ __launch_bounds__(256) void edge2_kernel(
    const float* __restrict__ as2p, const float* __restrict__ ad2p,
    const float* __restrict__ b2p, float* __restrict__ out, int n) {
    int warp = (blockIdx.x * blockDim.x + threadIdx.x) >> 5;
    int lane = threadIdx.x & 31;
    if (warp >= n) return;
    float a_s2 = as2p[0], a_d2 = ad2p[0], b2 = b2p[0];
    int beg = g_offs[warp], end = g_offs[warp + 1];
    float adv = g_h2[warp] * a_d2;
    unsigned full = 0xFFFFFFFFu;

    float s = 0.f, ws = 0.f;
    for (int j = beg + lane; j < end; j += 32) {
        float hv = g_h2[g_esrc[j]];
        float e = hv * a_s2 + adv;
        e = e > 0.f ? e : 0.2f * e;
        float ex = __expf(e);
        s += ex;
        ws += ex * hv;
    }
    #pragma unroll
    for (int o = 16; o > 0; o >>= 1) {
        s  += __shfl_xor_sync(full, s, o);
        ws += __shfl_xor_sync(full, ws, o);
    }
    if (lane == 0) {
        float v = ws / (s + 1e-16f) + b2;
        out[warp] = 1.f / (1.f + __expf(-v));
    }
}

// ---------------- launch ----------------
extern "C" void kernel_launch(void* const* d_in, const int* in_sizes, int n_in,
                              void* d_out, int out_size) {
    const float* x      = (const float*)d_in[0];
    const void*  ei     = d_in[1];             // int32 or int64 — probed on device
    const float* W1     = (const float*)d_in[2];
    const float* asrc1  = (const float*)d_in[3];
    const float* adst1  = (const float*)d_in[4];
    const float* bias1  = (const float*)d_in[5];
    const float* W2     = (const float*)d_in[6];
    const float* asrc2  = (const float*)d_in[7];
    const float* adst2  = (const float*)d_in[8];
    const float* bias2  = (const float*)d_in[9];
    float* out = (float*)d_out;

    int N = in_sizes[0] / FIN;
    int E = in_sizes[1] / 2;
    int NB = (N + SCAN_B - 1) / SCAN_B;
    int NBg = (N + 31) / 32;                   // gemm blocks
    int NBs = (E + N + 255) / 256;             // scatter blocks

    // CSR build (by destination); dtype probe fused into init
    init_deg_kernel<<<(N + 255) / 256, 256>>>(ei, E, N);
    count_kernel<<<(E + 255) / 256, 256>>>(ei, E);
    reduce_kernel<<<NB, SCAN_B>>>(N);
    bscan_kernel<<<1, SCAN_B>>>(NB);
    offs_kernel<<<NB, SCAN_B>>>(N);

    // GEMM1 (+alpha epilogue) and scatter run concurrently in one fat kernel
    gemm_scatter_kernel<<<NBg + NBs, 256>>>(x, W1, asrc1, adst1, ei, E, N, NBg);

    // layer 1: warp per node, all heads
    edge1_kernel<<<(N * 32 + 255) / 256, 256>>>(bias1, W2, N);

    // layer 2 (warp per node)
    edge2_kernel<<<(N * 32 + 255) / 256, 256>>>(asrc2, adst2, bias2, out, N);
}